// round 1
// baseline (speedup 1.0000x reference)
#include <cuda_runtime.h>
#include <math.h>

// Problem constants
constexpr int B_   = 16;
constexpr int N_   = 1024;
constexpr int CIN_ = 64;
constexpr int HID_ = 128;
constexpr int H_   = 8;
constexpr int COUT_= 64;
constexpr int CAT_ = HID_ * H_;   // 1024

// Scratch (device globals — no allocation allowed)
__device__ float g_feat[B_ * N_ * CAT_];   // layer-1 per-head features, concat layout [b][n][h*128+d]
__device__ float g_cat [B_ * N_ * CAT_];   // leakyrelu(attn1 + bh) in concat layout
__device__ float g_h2  [B_ * N_ * COUT_];  // layer-2 features

// ---------------------------------------------------------------------------
// Kernel 1: g_feat[bn][h*128+d] = flow_x[bn] @ Wh[h]   (M=16384, K=64, Nc=128)
// ---------------------------------------------------------------------------
__global__ __launch_bounds__(256) void gemm1_kernel(const float* __restrict__ x,
                                                    const float* __restrict__ Wh) {
    __shared__ float sX[64][CIN_];    // 16 KB
    __shared__ float sW[CIN_][HID_];  // 32 KB
    const int tid = threadIdx.x;
    const int tx = tid & 15, ty = tid >> 4;
    const int bn0 = blockIdx.x * 64;
    const int h = blockIdx.y;
    const float* Wp = Wh + (size_t)h * CIN_ * HID_;

    for (int i = tid; i < CIN_ * HID_; i += 256) sW[i / HID_][i % HID_] = Wp[i];
    for (int i = tid; i < 64 * CIN_; i += 256)
        sX[i / CIN_][i % CIN_] = x[(size_t)(bn0 + i / CIN_) * CIN_ + (i % CIN_)];
    __syncthreads();

    float acc[4][8];
#pragma unroll
    for (int i = 0; i < 4; i++)
#pragma unroll
        for (int j = 0; j < 8; j++) acc[i][j] = 0.f;

#pragma unroll 4
    for (int k = 0; k < CIN_; k++) {
        float xv[4], wv[8];
#pragma unroll
        for (int i = 0; i < 4; i++) xv[i] = sX[ty * 4 + i][k];
#pragma unroll
        for (int j = 0; j < 8; j++) wv[j] = sW[k][tx + 16 * j];
#pragma unroll
        for (int i = 0; i < 4; i++)
#pragma unroll
            for (int j = 0; j < 8; j++) acc[i][j] = fmaf(xv[i], wv[j], acc[i][j]);
    }

#pragma unroll
    for (int i = 0; i < 4; i++)
#pragma unroll
        for (int j = 0; j < 8; j++)
            g_feat[(size_t)(bn0 + ty * 4 + i) * CAT_ + h * HID_ + tx + 16 * j] = acc[i][j];
}

// ---------------------------------------------------------------------------
// Fused masked-softmax attention (flash-style), Q=K=V=feat.
//   LAYER 1: feat=g_feat (stride 1024), out=g_cat, epilogue = lrelu(o + bh[h])
//   LAYER 2: feat=g_h2  (stride 64),   out=d_out, epilogue = lrelu(o + b_out)
// Block: 64 query rows, 256 threads (16x16). Per-thread: 4 rows, D/16 out cols.
// ---------------------------------------------------------------------------
template <int D, int LAYER>
__global__ __launch_bounds__(256, 2) void attn_kernel(const float* __restrict__ graph,
                                                      const float* __restrict__ bias,
                                                      float* __restrict__ out2) {
    constexpr int LD  = D + 4;   // float4-aligned (mod 4 == 0), col-stride mod 32 == 4
    constexpr int PLD = 68;
    constexpr int CPT = D / 16;  // cols per thread (8 or 4)
    extern __shared__ float smem[];
    float* sQ = smem;
    float* sK = smem + 64 * LD;
    float* sP = sK + 64 * LD;

    const int tid = threadIdx.x;
    const int tx = tid & 15, ty = tid >> 4;
    const int n0 = blockIdx.x * 64;
    const int b  = blockIdx.y;
    const int h  = blockIdx.z;

    const int fstride = (LAYER == 1) ? CAT_ : COUT_;
    const float* feat = (LAYER == 1) ? g_feat : g_h2;
    float* outp       = (LAYER == 1) ? g_cat : out2;
    const float* Qb = feat + (size_t)b * N_ * fstride + h * D;
    float* Ob       = outp + (size_t)b * N_ * fstride + h * D;
    const float* bias_h = bias + h * D;

    // Q tile -> smem
    for (int i = tid; i < 64 * D; i += 256) {
        int r = i / D, c = i - r * D;
        sQ[r * LD + c] = Qb[(size_t)(n0 + r) * fstride + c];
    }

    float o[4][CPT];
#pragma unroll
    for (int i = 0; i < 4; i++)
#pragma unroll
        for (int c = 0; c < CPT; c++) o[i][c] = 0.f;
    float mrow[4] = {-INFINITY, -INFINITY, -INFINITY, -INFINITY};
    float lrow[4] = {0.f, 0.f, 0.f, 0.f};

    __syncthreads();

    for (int m0 = 0; m0 < N_; m0 += 64) {
        // K/V tile -> smem
        for (int i = tid; i < 64 * D; i += 256) {
            int r = i / D, c = i - r * D;
            sK[r * LD + c] = Qb[(size_t)(m0 + r) * fstride + c];
        }
        __syncthreads();

        // adjacency mask (graph is 4MB, L2-resident; overlaps with score compute)
        float g[4][4];
#pragma unroll
        for (int i = 0; i < 4; i++)
#pragma unroll
            for (int j = 0; j < 4; j++)
                g[i][j] = __ldg(&graph[(size_t)(n0 + ty * 4 + i) * N_ + m0 + tx + 16 * j]);

        // S = Q K^T  (4x4 per thread, cols = tx + 16*j : conflict-free)
        float s[4][4];
#pragma unroll
        for (int i = 0; i < 4; i++)
#pragma unroll
            for (int j = 0; j < 4; j++) s[i][j] = 0.f;

#pragma unroll 4
        for (int d0 = 0; d0 < D; d0 += 4) {
            float4 qv[4], kv[4];
#pragma unroll
            for (int i = 0; i < 4; i++)
                qv[i] = *(const float4*)(sQ + (ty * 4 + i) * LD + d0);
#pragma unroll
            for (int j = 0; j < 4; j++)
                kv[j] = *(const float4*)(sK + (tx + 16 * j) * LD + d0);
#pragma unroll
            for (int i = 0; i < 4; i++)
#pragma unroll
                for (int j = 0; j < 4; j++) {
                    s[i][j] = fmaf(qv[i].x, kv[j].x, s[i][j]);
                    s[i][j] = fmaf(qv[i].y, kv[j].y, s[i][j]);
                    s[i][j] = fmaf(qv[i].z, kv[j].z, s[i][j]);
                    s[i][j] = fmaf(qv[i].w, kv[j].w, s[i][j]);
                }
        }

        // mask: graph==0 -> -1e16 (matches torch/jax masked_fill semantics)
#pragma unroll
        for (int i = 0; i < 4; i++)
#pragma unroll
            for (int j = 0; j < 4; j++)
                s[i][j] = (g[i][j] != 0.f) ? s[i][j] : -1e16f;

        // online softmax per row (row shared by 16 lanes of same ty; aligned in warp)
#pragma unroll
        for (int i = 0; i < 4; i++) {
            float tm = fmaxf(fmaxf(s[i][0], s[i][1]), fmaxf(s[i][2], s[i][3]));
#pragma unroll
            for (int off = 8; off >= 1; off >>= 1)
                tm = fmaxf(tm, __shfl_xor_sync(0xffffffffu, tm, off));
            float nm = fmaxf(mrow[i], tm);
            float scale = __expf(mrow[i] - nm);
            float ls = 0.f;
#pragma unroll
            for (int j = 0; j < 4; j++) {
                s[i][j] = __expf(s[i][j] - nm);
                ls += s[i][j];
            }
#pragma unroll
            for (int off = 8; off >= 1; off >>= 1)
                ls += __shfl_xor_sync(0xffffffffu, ls, off);
            lrow[i] = lrow[i] * scale + ls;
            mrow[i] = nm;
#pragma unroll
            for (int c = 0; c < CPT; c++) o[i][c] *= scale;
#pragma unroll
            for (int j = 0; j < 4; j++) sP[(ty * 4 + i) * PLD + tx + 16 * j] = s[i][j];
        }
        __syncthreads();

        // O += P @ V  (V tile == K tile; cols = tx + 16*c : conflict-free)
#pragma unroll 4
        for (int m4 = 0; m4 < 64; m4 += 4) {
            float4 pv[4];
#pragma unroll
            for (int i = 0; i < 4; i++)
                pv[i] = *(const float4*)(sP + (ty * 4 + i) * PLD + m4);
            float pa[4][4];
#pragma unroll
            for (int i = 0; i < 4; i++) {
                pa[i][0] = pv[i].x; pa[i][1] = pv[i].y;
                pa[i][2] = pv[i].z; pa[i][3] = pv[i].w;
            }
#pragma unroll
            for (int mm = 0; mm < 4; mm++) {
#pragma unroll
                for (int c = 0; c < CPT; c++) {
                    float kv = sK[(m4 + mm) * LD + tx + 16 * c];
#pragma unroll
                    for (int i = 0; i < 4; i++)
                        o[i][c] = fmaf(pa[i][mm], kv, o[i][c]);
                }
            }
        }
        __syncthreads();
    }

    // epilogue: normalize, bias, leaky_relu(0.01)
#pragma unroll
    for (int i = 0; i < 4; i++) {
        float inv = 1.f / lrow[i];
#pragma unroll
        for (int c = 0; c < CPT; c++) {
            float v = fmaf(o[i][c] * inv, 1.f, bias_h[tx + 16 * c]);
            v = (v > 0.f) ? v : 0.01f * v;
            Ob[(size_t)(n0 + ty * 4 + i) * fstride + tx + 16 * c] = v;
        }
    }
}

// ---------------------------------------------------------------------------
// Kernel 3: g_h2 = g_cat(activated) @ W_out   (M=16384, K=1024, Nc=64)
// ---------------------------------------------------------------------------
__global__ __launch_bounds__(256) void gemm2_kernel(const float* __restrict__ Wout) {
    __shared__ float sA[64][68];
    __shared__ float sB[64][68];
    const int tid = threadIdx.x;
    const int tx = tid & 15, ty = tid >> 4;
    const int bn0 = blockIdx.x * 64;

    float acc[4][4];
#pragma unroll
    for (int i = 0; i < 4; i++)
#pragma unroll
        for (int j = 0; j < 4; j++) acc[i][j] = 0.f;

    for (int k0 = 0; k0 < CAT_; k0 += 64) {
        for (int i = tid; i < 64 * 64; i += 256) {
            int r = i >> 6, c = i & 63;
            sA[r][c] = g_cat[(size_t)(bn0 + r) * CAT_ + k0 + c];
            sB[r][c] = Wout[(size_t)(k0 + r) * COUT_ + c];
        }
        __syncthreads();
#pragma unroll 4
        for (int k = 0; k < 64; k++) {
            float av[4], bv[4];
#pragma unroll
            for (int i = 0; i < 4; i++) av[i] = sA[ty * 4 + i][k];
#pragma unroll
            for (int j = 0; j < 4; j++) bv[j] = sB[k][tx + 16 * j];
#pragma unroll
            for (int i = 0; i < 4; i++)
#pragma unroll
                for (int j = 0; j < 4; j++) acc[i][j] = fmaf(av[i], bv[j], acc[i][j]);
        }
        __syncthreads();
    }

#pragma unroll
    for (int i = 0; i < 4; i++)
#pragma unroll
        for (int j = 0; j < 4; j++)
            g_h2[(size_t)(bn0 + ty * 4 + i) * COUT_ + tx + 16 * j] = acc[i][j];
}

// ---------------------------------------------------------------------------
extern "C" void kernel_launch(void* const* d_in, const int* in_sizes, int n_in,
                              void* d_out, int out_size) {
    const float* flow_x = (const float*)d_in[0];
    const float* graph  = (const float*)d_in[1];
    const float* Wh     = (const float*)d_in[2];
    const float* bh     = (const float*)d_in[3];
    const float* W_out  = (const float*)d_in[4];
    const float* b_out  = (const float*)d_in[5];
    float* out = (float*)d_out;

    constexpr int SMEM128 = (64 * (128 + 4) * 2 + 64 * 68) * 4;  // 84992 B
    constexpr int SMEM64  = (64 * (64 + 4) * 2 + 64 * 68) * 4;   // 52224 B
    cudaFuncSetAttribute(attn_kernel<128, 1>, cudaFuncAttributeMaxDynamicSharedMemorySize, SMEM128);
    cudaFuncSetAttribute(attn_kernel<64, 2>,  cudaFuncAttributeMaxDynamicSharedMemorySize, SMEM64);

    gemm1_kernel<<<dim3(B_ * N_ / 64, H_), 256>>>(flow_x, Wh);
    attn_kernel<128, 1><<<dim3(N_ / 64, B_, H_), 256, SMEM128>>>(graph, bh, nullptr);
    gemm2_kernel<<<dim3(B_ * N_ / 64), 256>>>(W_out);
    attn_kernel<64, 2><<<dim3(N_ / 64, B_, 1), 256, SMEM64>>>(graph, b_out, out);
}